// round 12
// baseline (speedup 1.0000x reference)
#include <cuda_runtime.h>
#include <cuda_bf16.h>
#include <math.h>
#include <cstdint>

#define LDIM 4096
#define HDIM 64
#define BDIM 32
#define BH   2048     // BDIM*HDIM
#define NK   128      // 64 real + 64 imag
#define KSPLIT 16
#define KPC  256      // LDIM / KSPLIT

typedef unsigned long long u64;

__device__ __forceinline__ uint32_t smem_to_u32(const void* p) {
    uint32_t a;
    asm("{ .reg .u64 tmp; cvta.to.shared.u64 tmp, %1; cvt.u32.u64 %0, tmp; }"
        : "=r"(a) : "l"(p));
    return a;
}

#define CP_ASYNC16(dst, src) \
    asm volatile("cp.async.cg.shared.global [%0], [%1], 16;" \
                 :: "r"(dst), "l"(src))
#define CP_COMMIT() asm volatile("cp.async.commit_group;")
#define CP_WAIT(n)  asm volatile("cp.async.wait_group %0;" :: "n"(n))

#define LDMATRIX_X4(r0, r1, r2, r3, addr) \
    asm volatile("ldmatrix.sync.aligned.m8n8.x4.shared.b16 {%0,%1,%2,%3}, [%4];" \
                 : "=r"(r0), "=r"(r1), "=r"(r2), "=r"(r3) : "r"(addr))

#define LDMATRIX_X4_T(r0, r1, r2, r3, addr) \
    asm volatile("ldmatrix.sync.aligned.m8n8.x4.trans.shared.b16 {%0,%1,%2,%3}, [%4];" \
                 : "=r"(r0), "=r"(r1), "=r"(r2), "=r"(r3) : "r"(addr))

#define MMA_16816(d, a, b0, b1) \
    asm volatile("mma.sync.aligned.m16n8k16.row.col.f32.bf16.bf16.f32 " \
                 "{%0,%1,%2,%3}, {%4,%5,%6,%7}, {%8,%9}, {%0,%1,%2,%3};" \
                 : "+f"((d)[0]), "+f"((d)[1]), "+f"((d)[2]), "+f"((d)[3]) \
                 : "r"((a)[0]), "r"((a)[1]), "r"((a)[2]), "r"((a)[3]), \
                   "r"(b0), "r"(b1))

// ---------------- device scratch ----------------
__device__ __nv_bfloat16 g_x0h[(size_t)BH * LDIM];  // 16 MB
__device__ __nv_bfloat16 g_x0l[(size_t)BH * LDIM];  // 16 MB
__device__ __nv_bfloat16 g_x1h[(size_t)BH * LDIM];  // 16 MB
__device__ __nv_bfloat16 g_x1l[(size_t)BH * LDIM];  // 16 MB
__device__ float g_cpart[(size_t)KSPLIT * BH * NK]; // 16 MB
__device__ float g_xfT[(size_t)NK * BH];            // 1 MB   [kk][bh]
__device__ float g_g[(size_t)BH * NK];              // 1 MB   [b*64+o][kk]
__device__ __nv_bfloat16 g_trigIh[(size_t)NK * LDIM];  // 1 MB  [kk][l] bf16 hi
__device__ __nv_bfloat16 g_trigIl[(size_t)NK * LDIM];  // 1 MB  [kk][l] bf16 lo
__device__ float g_wT[(size_t)4 * 64 * 2 * 4096];   // 8 MB

__device__ __forceinline__ float gelu_tanh(float v) {
    const float c0 = 0.7978845608028654f;
    float inner = c0 * (v + 0.044715f * v * v * v);
    return 0.5f * v * (1.0f + tanhf(inner));
}
__device__ __forceinline__ float gelu_fast(float v) {
    const float c0 = 0.7978845608028654f;
    float inner = c0 * (v + 0.044715f * v * v * v);
    float th;
    asm("tanh.approx.f32 %0, %1;" : "=f"(th) : "f"(inner));
    return 0.5f * v * (1.0f + th);
}

// ---------------- trig tables (bf16 hi/lo) ----------------
__global__ void trig_kernel() {
    int idx = blockIdx.x * 256 + threadIdx.x;   // < 128*4096
    int kk = idx >> 12, l = idx & 4095;
    int k = kk & 63;
    int m = (k * l) & (LDIM - 1);
    float sn, cn;
    sincospif((float)m * (1.0f / 2048.0f), &sn, &cn);
    float v = (kk < 64) ? cn : -sn;
    size_t off = (size_t)kk * LDIM + l;
    __nv_bfloat16 hi = __float2bfloat16(v);
    g_trigIh[off] = hi;
    g_trigIl[off] = __float2bfloat16(v - __bfloat162float(hi));
}

// ---------------- spec weight transpose ----------------
__global__ __launch_bounds__(1024) void wtrans_kernel(
    const float* __restrict__ wr, const float* __restrict__ wi)
{
    __shared__ float tr[32][33];
    __shared__ float ti[32][33];
    int oi0 = blockIdx.x * 32;
    int k0  = blockIdx.y * 32;
    int layer = blockIdx.z;
    int tx = threadIdx.x & 31, ty = threadIdx.x >> 5;
    size_t rbase = ((size_t)layer * 4096 + oi0 + ty) * 64 + k0 + tx;
    tr[ty][tx] = wr[rbase];
    ti[ty][tx] = wi[rbase];
    __syncthreads();
    int k = k0 + ty;
    size_t wbase = ((size_t)(layer * 64 + k) * 2) * 4096 + oi0 + tx;
    g_wT[wbase]        = tr[tx][ty];
    g_wT[wbase + 4096] = ti[tx][ty];
}

// ---------------- lift (writes bf16 hi/lo) ----------------
__global__ __launch_bounds__(128) void lift_kernel(
    const float* __restrict__ u, const float* __restrict__ z,
    const float* __restrict__ w_lift, const float* __restrict__ b_lift,
    __nv_bfloat16* __restrict__ xh, __nv_bfloat16* __restrict__ xl)
{
    int b = blockIdx.y;
    int l = blockIdx.x * 128 + threadIdx.x;
    __shared__ float sw[64 * 16];
    __shared__ float sb[64];
    int t = threadIdx.x;
    for (int e = t; e < 1024; e += 128) sw[e] = w_lift[e];
    if (t < 64) sb[t] = b_lift[t];
    __syncthreads();
    float uv[16];
#pragma unroll
    for (int c = 0; c < 8; c++) uv[c] = u[((size_t)b * LDIM + l) * 8 + c];
#pragma unroll
    for (int c = 0; c < 8; c++) uv[8 + c] = z[b * 8 + c];
    for (int h = 0; h < 64; h++) {
        float acc = sb[h];
#pragma unroll
        for (int c = 0; c < 16; c++) acc += sw[h * 16 + c] * uv[c];
        size_t off = ((size_t)(b * 64 + h)) * LDIM + l;
        __nv_bfloat16 hi = __float2bfloat16(acc);
        xh[off] = hi;
        xl[off] = __float2bfloat16(acc - __bfloat162float(hi));
    }
}

// ---------------- forward DFT via mma.sync, 3-stage ring, XOR swizzle ----
// grid (16 Mtiles, KSPLIT). CTA 256 thr = 8 warps (4 m x 2 n), warp 32x64.
// chunks of 32 l; tile [128 rows][64 B], chunk c at physical c^((r>>1)&3).
// MMA schedule is term-major: 16 independent accumulators per pass -> no RAW.
#define DCHK 32
#define DTILE_B (128 * 64)              // 8192
#define DBUF_B (4 * DTILE_B)            // 32768
#define DSTAGES 3
#define DFT_SMEM (DSTAGES * DBUF_B)     // 98304
#define DNCHK (KPC / DCHK)              // 8

__device__ __forceinline__ void dft_stage(
    uint32_t sb, int buf, int lc, int bh0, int t,
    const __nv_bfloat16* xh, const __nv_bfloat16* xl)
{
#pragma unroll
    for (int i = 0; i < 8; i++) {
        const int tile = i >> 1;
        int q = t + 256 * (i & 1);
        int r = q >> 2, uu = q & 3;
        const __nv_bfloat16* src;
        if (tile == 0)      src = xh + ((size_t)(bh0 + r)) * LDIM;
        else if (tile == 1) src = xl + ((size_t)(bh0 + r)) * LDIM;
        else if (tile == 2) src = g_trigIh + (size_t)r * LDIM;
        else                src = g_trigIl + (size_t)r * LDIM;
        uint32_t dst = sb + buf * DBUF_B + tile * DTILE_B + r * 64
                       + ((uu ^ ((r >> 1) & 3)) << 4);
        CP_ASYNC16(dst, src + lc + uu * 8);
    }
    CP_COMMIT();
}

__global__ void __launch_bounds__(256, 2) dft_mma_kernel(
    const __nv_bfloat16* __restrict__ xh,
    const __nv_bfloat16* __restrict__ xl,
    float* __restrict__ cpart)
{
    extern __shared__ char smem[];
    uint32_t sb = smem_to_u32(smem);
    int t = threadIdx.x;
    int lane = t & 31, w = t >> 5;
    int wm = w & 3, wn = w >> 2;
    int bh0 = blockIdx.x * 128;
    int l0  = blockIdx.y * KPC;

    int lrow = lane & 15, lhi = lane >> 4;
    uint32_t arow[2], brow[4];
    uint32_t arsw[2], brsw[4];
#pragma unroll
    for (int mi = 0; mi < 2; mi++) {
        int row = 32 * wm + 16 * mi + lrow;
        arow[mi] = (uint32_t)(row * 64);
        arsw[mi] = (uint32_t)((row >> 1) & 3);
    }
#pragma unroll
    for (int ni = 0; ni < 4; ni++) {
        int row = 64 * wn + 16 * ni + lrow;
        brow[ni] = (uint32_t)(row * 64);
        brsw[ni] = (uint32_t)((row >> 1) & 3);
    }

    float d[2][8][4];
#pragma unroll
    for (int mi = 0; mi < 2; mi++)
#pragma unroll
        for (int ng = 0; ng < 8; ng++)
#pragma unroll
            for (int j = 0; j < 4; j++) d[mi][ng][j] = 0.f;

    dft_stage(sb, 0, l0, bh0, t, xh, xl);
    dft_stage(sb, 1, l0 + DCHK, bh0, t, xh, xl);

    for (int c = 0; c < DNCHK; c++) {
        if (c + 1 < DNCHK) CP_WAIT(1); else CP_WAIT(0);
        __syncthreads();
        if (c + 2 < DNCHK)
            dft_stage(sb, (c + 2) % DSTAGES, l0 + (c + 2) * DCHK, bh0, t, xh, xl);
        uint32_t base = sb + (c % DSTAGES) * DBUF_B;
#pragma unroll
        for (int s = 0; s < 2; s++) {
            uint32_t cl = (uint32_t)(s * 2) + (uint32_t)lhi;  // logical chunk
            uint32_t aH[2][4], aL[2][4], bHf[4][4], bLf[4][4];
#pragma unroll
            for (int mi = 0; mi < 2; mi++) {
                uint32_t aoff = arow[mi] + ((cl ^ arsw[mi]) << 4);
                LDMATRIX_X4(aH[mi][0], aH[mi][1], aH[mi][2], aH[mi][3],
                            base + 0 * DTILE_B + aoff);
                LDMATRIX_X4(aL[mi][0], aL[mi][1], aL[mi][2], aL[mi][3],
                            base + 1 * DTILE_B + aoff);
            }
#pragma unroll
            for (int ni = 0; ni < 4; ni++) {
                uint32_t boff = brow[ni] + ((cl ^ brsw[ni]) << 4);
                LDMATRIX_X4(bHf[ni][0], bHf[ni][1], bHf[ni][2], bHf[ni][3],
                            base + 2 * DTILE_B + boff);
                LDMATRIX_X4(bLf[ni][0], bLf[ni][1], bLf[ni][2], bLf[ni][3],
                            base + 3 * DTILE_B + boff);
            }
            // term-major schedule: each pass hits 16 distinct accumulators
#pragma unroll
            for (int mi = 0; mi < 2; mi++)
#pragma unroll
                for (int ni = 0; ni < 4; ni++)
#pragma unroll
                    for (int sub = 0; sub < 2; sub++)
                        MMA_16816(d[mi][ni * 2 + sub], aH[mi],
                                  bHf[ni][sub], bHf[ni][sub + 2]);
#pragma unroll
            for (int mi = 0; mi < 2; mi++)
#pragma unroll
                for (int ni = 0; ni < 4; ni++)
#pragma unroll
                    for (int sub = 0; sub < 2; sub++)
                        MMA_16816(d[mi][ni * 2 + sub], aL[mi],
                                  bHf[ni][sub], bHf[ni][sub + 2]);
#pragma unroll
            for (int mi = 0; mi < 2; mi++)
#pragma unroll
                for (int ni = 0; ni < 4; ni++)
#pragma unroll
                    for (int sub = 0; sub < 2; sub++)
                        MMA_16816(d[mi][ni * 2 + sub], aH[mi],
                                  bLf[ni][sub], bLf[ni][sub + 2]);
        }
    }

    float* cp = cpart + (size_t)blockIdx.y * BH * NK;
    int rbase = bh0 + 32 * wm + (lane >> 2);
    int cbase = 64 * wn + (lane & 3) * 2;
#pragma unroll
    for (int mi = 0; mi < 2; mi++) {
#pragma unroll
        for (int ng = 0; ng < 8; ng++) {
            int col = cbase + 8 * ng;
            int row = rbase + 16 * mi;
            *reinterpret_cast<float2*>(&cp[(size_t)row * NK + col]) =
                make_float2(d[mi][ng][0], d[mi][ng][1]);
            *reinterpret_cast<float2*>(&cp[(size_t)(row + 8) * NK + col]) =
                make_float2(d[mi][ng][2], d[mi][ng][3]);
        }
    }
}

// reduce split buffers -> xfT[kk][bh]
__global__ __launch_bounds__(256) void reduce_kernel(
    const float* __restrict__ cpart, float* __restrict__ xfT)
{
    int q = blockIdx.x * 256 + threadIdx.x;
    int idx = q * 4;
    int bh = idx >> 7, kk = idx & 127;
    float4 s = make_float4(0.f, 0.f, 0.f, 0.f);
#pragma unroll
    for (int p = 0; p < KSPLIT; p++) {
        float4 v = *reinterpret_cast<const float4*>(&cpart[(size_t)p * BH * NK + idx]);
        s.x += v.x; s.y += v.y; s.z += v.z; s.w += v.w;
    }
    xfT[(size_t)(kk + 0) * BH + bh] = s.x;
    xfT[(size_t)(kk + 1) * BH + bh] = s.y;
    xfT[(size_t)(kk + 2) * BH + bh] = s.z;
    xfT[(size_t)(kk + 3) * BH + bh] = s.w;
}

// ---------------- per-mode complex mix (one block per k, 512 thr) --------
__global__ __launch_bounds__(512) void mix_kernel(
    const float* __restrict__ xfT, float* __restrict__ g, int layer)
{
    int k = blockIdx.x;
    __shared__ float swr[64][65];
    __shared__ float swi[64][65];
    __shared__ float sxr[64][32];
    __shared__ float sxi[64][32];
    int t = threadIdx.x;
    const float* wTr = g_wT + ((size_t)(layer * 64 + k) * 2) * 4096;
    for (int e = t; e < 4096; e += 512) {
        int o = e >> 6, i = e & 63;
        swr[o][i] = wTr[e];
        swi[o][i] = wTr[4096 + e];
    }
    for (int e = t; e < 2048; e += 512) {
        int b = e >> 6, i = e & 63;
        int bh = b * 64 + i;
        sxr[i][b] = xfT[(size_t)k * BH + bh];
        sxi[i][b] = xfT[(size_t)(64 + k) * BH + bh];
    }
    __syncthreads();
    int o = t >> 3;
    int b0 = (t & 7) * 4;
    float ar[4] = {0, 0, 0, 0}, ai[4] = {0, 0, 0, 0};
    for (int i = 0; i < 64; i++) {
        float wrv = swr[o][i], wiv = swi[o][i];
#pragma unroll
        for (int j = 0; j < 4; j++) {
            float xr = sxr[i][b0 + j], xi = sxi[i][b0 + j];
            ar[j] += xr * wrv - xi * wiv;
            ai[j] += xr * wiv + xi * wrv;
        }
    }
    float scl = (k == 0) ? (1.0f / LDIM) : (2.0f / LDIM);
#pragma unroll
    for (int j = 0; j < 4; j++) {
        int b = b0 + j;
        g[((size_t)(b * 64 + o)) * NK + k] = ar[j] * scl;
        g[((size_t)(b * 64 + o)) * NK + 64 + k] = (k == 0) ? 0.0f : ai[j] * scl;
    }
}

// ---------------- fused iDFT + skip + bias + gelu via mma.sync -----------
// grid (32 l-tiles of 128, 32 b). CTA 256 thr = 8 warps (4 m x 2 n).
// K chunks of 32 (6 chunks: 4 trig, 2 xold), 3-stage ring, 1 sync/chunk.
// Term-major MMA schedule: 8 independent accumulators per pass.
#define APITCH 200                          // bf16 per A row
#define A_TILE_B (64 * APITCH * 2)          // 25600
#define BPITCH 272                          // bytes per B row (128 bf16 + pad)
#define IBTILE_B (32 * BPITCH)              // 8704
#define IBUF_B (2 * IBTILE_B)               // 17408
#define ISTAGES 3
#define OFF_AH 0
#define OFF_AL (A_TILE_B)
#define OFF_B  (2 * A_TILE_B)
#define IDFT_SMEM (2 * A_TILE_B + ISTAGES * IBUF_B)   // 103424
#define INCHK 6

__device__ __forceinline__ void idft_stage(
    uint32_t sbu, int buf, int c, int b, int l0, int t,
    const __nv_bfloat16* xoldh, const __nv_bfloat16* xoldl)
{
#pragma unroll
    for (int i = 0; i < 4; i++) {
        const int tile = i >> 1;              // 0 = hi, 1 = lo
        int q = t + 256 * (i & 1);
        int r = q >> 4, uu = q & 15;
        const __nv_bfloat16* src;
        if (c < 4) src = (tile ? g_trigIl : g_trigIh) + (size_t)(c * 32 + r) * LDIM;
        else       src = (tile ? xoldl : xoldh)
                         + ((size_t)(b * 64 + (c - 4) * 32 + r)) * LDIM;
        uint32_t dst = sbu + OFF_B + buf * IBUF_B + tile * IBTILE_B
                       + r * BPITCH + uu * 16;
        CP_ASYNC16(dst, src + l0 + uu * 8);
    }
    CP_COMMIT();
}

__global__ void __launch_bounds__(256, 2) idft_mma_kernel(
    const float* __restrict__ g,
    const __nv_bfloat16* __restrict__ xoldh, const __nv_bfloat16* __restrict__ xoldl,
    const float* __restrict__ w_skip, const float* __restrict__ b_skip,
    __nv_bfloat16* __restrict__ xnewh, __nv_bfloat16* __restrict__ xnewl, int layer)
{
    extern __shared__ char smem[];
    uint32_t sbu = smem_to_u32(smem);
    int t = threadIdx.x;
    int lane = t & 31, w = t >> 5;
    int wm = w & 3, wn = w >> 2;
    int b  = blockIdx.y;
    int l0 = blockIdx.x * 128;
    int lrow = lane & 15, lhi = lane >> 4;

    idft_stage(sbu, 0, 0, b, l0, t, xoldh, xoldl);

    // stage A = [64 o][192 kk] fp32 -> hi/lo bf16 (overlaps with B stage 0)
    for (int idx = t; idx < 64 * 192; idx += 256) {
        int row = idx / 192, col = idx - row * 192;
        float v = (col < 128)
            ? g[((size_t)(b * 64 + row)) * NK + col]
            : w_skip[((size_t)layer * 64 + row) * 64 + (col - 128)];
        __nv_bfloat16 hi = __float2bfloat16(v);
        __nv_bfloat16 lo = __float2bfloat16(v - __bfloat162float(hi));
        ((__nv_bfloat16*)(smem + OFF_AH))[row * APITCH + col] = hi;
        ((__nv_bfloat16*)(smem + OFF_AL))[row * APITCH + col] = lo;
    }

    idft_stage(sbu, 1, 1, b, l0, t, xoldh, xoldl);

    float d[8][4];
    {
        float bs0 = b_skip[layer * 64 + wm * 16 + (lane >> 2)];
        float bs1 = b_skip[layer * 64 + wm * 16 + (lane >> 2) + 8];
#pragma unroll
        for (int ng = 0; ng < 8; ng++) {
            d[ng][0] = bs0; d[ng][1] = bs0;
            d[ng][2] = bs1; d[ng][3] = bs1;
        }
    }

    uint32_t aoff = (uint32_t)((wm * 16 + lrow) * (APITCH * 2) + lhi * 16);
    uint32_t boff[4];
#pragma unroll
    for (int ni = 0; ni < 4; ni++)
        boff[ni] = (uint32_t)(lrow * BPITCH + (wn * 64 + ni * 16) * 2 + lhi * 16);

    for (int c = 0; c < INCHK; c++) {
        if (c + 1 < INCHK) CP_WAIT(1); else CP_WAIT(0);
        __syncthreads();
        if (c + 2 < INCHK)
            idft_stage(sbu, (c + 2) % ISTAGES, c + 2, b, l0, t, xoldh, xoldl);
        uint32_t bbase = sbu + OFF_B + (c % ISTAGES) * IBUF_B;
#pragma unroll
        for (int s = 0; s < 2; s++) {
            uint32_t aH[4], aL[4], bHf[4][4], bLf[4][4];
            uint32_t ash = (uint32_t)((c * 2 + s) * 32);
            LDMATRIX_X4(aH[0], aH[1], aH[2], aH[3], sbu + OFF_AH + aoff + ash);
            LDMATRIX_X4(aL[0], aL[1], aL[2], aL[3], sbu + OFF_AL + aoff + ash);
            uint32_t bsh = (uint32_t)(s * 16 * BPITCH);
#pragma unroll
            for (int ni = 0; ni < 4; ni++) {
                LDMATRIX_X4_T(bHf[ni][0], bHf[ni][1], bHf[ni][2], bHf[ni][3],
                              bbase + 0 * IBTILE_B + bsh + boff[ni]);
                LDMATRIX_X4_T(bLf[ni][0], bLf[ni][1], bLf[ni][2], bLf[ni][3],
                              bbase + 1 * IBTILE_B + bsh + boff[ni]);
            }
            // term-major schedule: 8 independent accumulators per pass
#pragma unroll
            for (int ni = 0; ni < 4; ni++)
#pragma unroll
                for (int sub = 0; sub < 2; sub++)
                    MMA_16816(d[ni * 2 + sub], aH,
                              bHf[ni][2 * sub], bHf[ni][2 * sub + 1]);
#pragma unroll
            for (int ni = 0; ni < 4; ni++)
#pragma unroll
                for (int sub = 0; sub < 2; sub++)
                    MMA_16816(d[ni * 2 + sub], aL,
                              bHf[ni][2 * sub], bHf[ni][2 * sub + 1]);
#pragma unroll
            for (int ni = 0; ni < 4; ni++)
#pragma unroll
                for (int sub = 0; sub < 2; sub++)
                    MMA_16816(d[ni * 2 + sub], aH,
                              bLf[ni][2 * sub], bLf[ni][2 * sub + 1]);
        }
    }

    int o0 = wm * 16 + (lane >> 2);
    int lc = l0 + wn * 64 + (lane & 3) * 2;
#pragma unroll
    for (int ng = 0; ng < 8; ng++) {
        int l = lc + ng * 8;
#pragma unroll
        for (int half = 0; half < 2; half++) {
            int o = o0 + 8 * half;
            float vx = gelu_fast(d[ng][2 * half]);
            float vy = gelu_fast(d[ng][2 * half + 1]);
            __nv_bfloat162 h2 = __floats2bfloat162_rn(vx, vy);
            float2 hv = __bfloat1622float2(h2);
            __nv_bfloat162 l2 = __floats2bfloat162_rn(vx - hv.x, vy - hv.y);
            size_t off = ((size_t)(b * 64 + o)) * LDIM + l;
            *reinterpret_cast<__nv_bfloat162*>(&xnewh[off]) = h2;
            *reinterpret_cast<__nv_bfloat162*>(&xnewl[off]) = l2;
        }
    }
}

// ---------------- layer-3 point eval + projection ----------------
__global__ __launch_bounds__(128) void final_kernel(
    const float* __restrict__ g,
    const __nv_bfloat16* __restrict__ x3h, const __nv_bfloat16* __restrict__ x3l,
    const float* __restrict__ w_skip, const float* __restrict__ b_skip,
    const float* __restrict__ w_p1, const float* __restrict__ b_p1,
    const float* __restrict__ w_p2, const float* __restrict__ b_p2,
    float* __restrict__ out)
{
    int b = blockIdx.x;
    int t = threadIdx.x;
    __shared__ float sv[64];
    __shared__ float sh[128];
    __shared__ float sxl[64];
    __shared__ float sc[64], ss[64];
    if (t < 64) {
        size_t off = ((size_t)(b * 64 + t)) * LDIM + (LDIM - 1);
        sxl[t] = __bfloat162float(x3h[off]) + __bfloat162float(x3l[off]);
        float sn, cn;
        sincospif((float)t / 2048.0f, &sn, &cn);
        sc[t] = cn; ss[t] = sn;
    }
    __syncthreads();
    if (t < 64) {
        int o = t;
        float acc = b_skip[3 * 64 + o];
        const float* go = g + ((size_t)(b * 64 + o)) * NK;
        for (int k = 0; k < 64; k++)
            acc += go[k] * sc[k] + go[64 + k] * ss[k];
        for (int i = 0; i < 64; i++)
            acc += w_skip[(3 * 64 + o) * 64 + i] * sxl[i];
        sv[o] = acc;
    }
    __syncthreads();
    {
        int p = t;
        float acc = b_p1[p];
        for (int o = 0; o < 64; o++) acc += w_p1[p * 64 + o] * sv[o];
        sh[p] = gelu_tanh(acc);
    }
    __syncthreads();
    if (t < 8) {
        float acc = b_p2[t];
        for (int p = 0; p < 128; p++) acc += w_p2[t * 128 + p] * sh[p];
        out[b * 8 + t] = acc;
    }
}

// ---------------- host launcher ------------------------------------------
extern "C" void kernel_launch(void* const* d_in, const int* in_sizes, int n_in,
                              void* d_out, int out_size)
{
    const float* u       = (const float*)d_in[0];
    const float* z       = (const float*)d_in[1];
    const float* w_lift  = (const float*)d_in[3];
    const float* b_lift  = (const float*)d_in[4];
    const float* spec_wr = (const float*)d_in[5];
    const float* spec_wi = (const float*)d_in[6];
    const float* w_skip  = (const float*)d_in[7];
    const float* b_skip  = (const float*)d_in[8];
    const float* w_p1    = (const float*)d_in[9];
    const float* b_p1    = (const float*)d_in[10];
    const float* w_p2    = (const float*)d_in[11];
    const float* b_p2    = (const float*)d_in[12];
    float* out = (float*)d_out;

    void *px0h, *px0l, *px1h, *px1l, *pcp, *pxf, *pgg;
    cudaGetSymbolAddress(&px0h, g_x0h);
    cudaGetSymbolAddress(&px0l, g_x0l);
    cudaGetSymbolAddress(&px1h, g_x1h);
    cudaGetSymbolAddress(&px1l, g_x1l);
    cudaGetSymbolAddress(&pcp, g_cpart);
    cudaGetSymbolAddress(&pxf, g_xfT);
    cudaGetSymbolAddress(&pgg, g_g);

    cudaFuncSetAttribute(dft_mma_kernel,
                         cudaFuncAttributeMaxDynamicSharedMemorySize, DFT_SMEM);
    cudaFuncSetAttribute(idft_mma_kernel,
                         cudaFuncAttributeMaxDynamicSharedMemorySize, IDFT_SMEM);

    trig_kernel<<<(NK * LDIM) / 256, 256>>>();
    wtrans_kernel<<<dim3(128, 2, 4), 1024>>>(spec_wr, spec_wi);
    lift_kernel<<<dim3(32, 32), 128>>>(u, z, w_lift, b_lift,
                                       (__nv_bfloat16*)px0h, (__nv_bfloat16*)px0l);

    __nv_bfloat16* xch = (__nv_bfloat16*)px0h;
    __nv_bfloat16* xcl = (__nv_bfloat16*)px0l;
    __nv_bfloat16* xnh = (__nv_bfloat16*)px1h;
    __nv_bfloat16* xnl = (__nv_bfloat16*)px1l;
    for (int layer = 0; layer < 4; layer++) {
        dft_mma_kernel<<<dim3(16, KSPLIT), 256, DFT_SMEM>>>(xch, xcl, (float*)pcp);
        reduce_kernel<<<(BH * NK / 4) / 256, 256>>>((float*)pcp, (float*)pxf);
        mix_kernel<<<64, 512>>>((float*)pxf, (float*)pgg, layer);
        if (layer < 3) {
            idft_mma_kernel<<<dim3(32, 32), 256, IDFT_SMEM>>>(
                (float*)pgg, xch, xcl, w_skip, b_skip, xnh, xnl, layer);
            __nv_bfloat16* th = xch; xch = xnh; xnh = th;
            __nv_bfloat16* tl = xcl; xcl = xnl; xnl = tl;
        }
    }
    final_kernel<<<32, 128>>>((float*)pgg, xch, xcl, w_skip, b_skip,
                              w_p1, b_p1, w_p2, b_p2, out);
}

// round 13
// speedup vs baseline: 1.0097x; 1.0097x over previous
#include <cuda_runtime.h>
#include <cuda_bf16.h>
#include <math.h>
#include <cstdint>

#define LDIM 4096
#define HDIM 64
#define BDIM 32
#define BH   2048     // BDIM*HDIM
#define NK   128      // 64 real + 64 imag
#define KSPLIT 16
#define KPC  256      // LDIM / KSPLIT

typedef unsigned long long u64;

__device__ __forceinline__ uint32_t smem_to_u32(const void* p) {
    uint32_t a;
    asm("{ .reg .u64 tmp; cvta.to.shared.u64 tmp, %1; cvt.u32.u64 %0, tmp; }"
        : "=r"(a) : "l"(p));
    return a;
}

#define CP_ASYNC16(dst, src) \
    asm volatile("cp.async.cg.shared.global [%0], [%1], 16;" \
                 :: "r"(dst), "l"(src))
#define CP_COMMIT() asm volatile("cp.async.commit_group;")
#define CP_WAIT(n)  asm volatile("cp.async.wait_group %0;" :: "n"(n))

#define LDMATRIX_X4(r0, r1, r2, r3, addr) \
    asm volatile("ldmatrix.sync.aligned.m8n8.x4.shared.b16 {%0,%1,%2,%3}, [%4];" \
                 : "=r"(r0), "=r"(r1), "=r"(r2), "=r"(r3) : "r"(addr))

#define LDMATRIX_X4_T(r0, r1, r2, r3, addr) \
    asm volatile("ldmatrix.sync.aligned.m8n8.x4.trans.shared.b16 {%0,%1,%2,%3}, [%4];" \
                 : "=r"(r0), "=r"(r1), "=r"(r2), "=r"(r3) : "r"(addr))

#define MMA_16816(d, a, b0, b1) \
    asm volatile("mma.sync.aligned.m16n8k16.row.col.f32.bf16.bf16.f32 " \
                 "{%0,%1,%2,%3}, {%4,%5,%6,%7}, {%8,%9}, {%0,%1,%2,%3};" \
                 : "+f"((d)[0]), "+f"((d)[1]), "+f"((d)[2]), "+f"((d)[3]) \
                 : "r"((a)[0]), "r"((a)[1]), "r"((a)[2]), "r"((a)[3]), \
                   "r"(b0), "r"(b1))

// ---------------- device scratch ----------------
__device__ __nv_bfloat16 g_x0h[(size_t)BH * LDIM];  // 16 MB
__device__ __nv_bfloat16 g_x0l[(size_t)BH * LDIM];  // 16 MB
__device__ __nv_bfloat16 g_x1h[(size_t)BH * LDIM];  // 16 MB
__device__ __nv_bfloat16 g_x1l[(size_t)BH * LDIM];  // 16 MB
__device__ float g_cpart[(size_t)KSPLIT * BH * NK]; // 16 MB
__device__ float g_xfT[(size_t)NK * BH];            // 1 MB   [kk][bh]
__device__ float g_g[(size_t)BH * NK];              // 1 MB   [b*64+o][kk] fp32
__device__ __nv_bfloat16 g_gh[(size_t)BH * NK];     // 0.5 MB bf16 hi
__device__ __nv_bfloat16 g_gl[(size_t)BH * NK];     // 0.5 MB bf16 lo
__device__ __nv_bfloat16 g_wsh[4 * 64 * 64];        // w_skip bf16 hi
__device__ __nv_bfloat16 g_wsl[4 * 64 * 64];        // w_skip bf16 lo
__device__ __nv_bfloat16 g_trigIh[(size_t)NK * LDIM];  // 1 MB  [kk][l] bf16 hi
__device__ __nv_bfloat16 g_trigIl[(size_t)NK * LDIM];  // 1 MB  [kk][l] bf16 lo
__device__ float g_wT[(size_t)4 * 64 * 2 * 4096];   // 8 MB

__device__ __forceinline__ float gelu_tanh(float v) {
    const float c0 = 0.7978845608028654f;
    float inner = c0 * (v + 0.044715f * v * v * v);
    return 0.5f * v * (1.0f + tanhf(inner));
}
__device__ __forceinline__ float gelu_fast(float v) {
    const float c0 = 0.7978845608028654f;
    float inner = c0 * (v + 0.044715f * v * v * v);
    float th;
    asm("tanh.approx.f32 %0, %1;" : "=f"(th) : "f"(inner));
    return 0.5f * v * (1.0f + th);
}

// ---------------- trig tables (bf16 hi/lo) ----------------
__global__ void trig_kernel() {
    int idx = blockIdx.x * 256 + threadIdx.x;   // < 128*4096
    int kk = idx >> 12, l = idx & 4095;
    int k = kk & 63;
    int m = (k * l) & (LDIM - 1);
    float sn, cn;
    sincospif((float)m * (1.0f / 2048.0f), &sn, &cn);
    float v = (kk < 64) ? cn : -sn;
    size_t off = (size_t)kk * LDIM + l;
    __nv_bfloat16 hi = __float2bfloat16(v);
    g_trigIh[off] = hi;
    g_trigIl[off] = __float2bfloat16(v - __bfloat162float(hi));
}

// ---------------- w_skip bf16 hi/lo split ----------------
__global__ void wskip_kernel(const float* __restrict__ w_skip) {
    int idx = blockIdx.x * 256 + threadIdx.x;   // < 4*64*64
    float v = w_skip[idx];
    __nv_bfloat16 hi = __float2bfloat16(v);
    g_wsh[idx] = hi;
    g_wsl[idx] = __float2bfloat16(v - __bfloat162float(hi));
}

// ---------------- spec weight transpose ----------------
__global__ __launch_bounds__(1024) void wtrans_kernel(
    const float* __restrict__ wr, const float* __restrict__ wi)
{
    __shared__ float tr[32][33];
    __shared__ float ti[32][33];
    int oi0 = blockIdx.x * 32;
    int k0  = blockIdx.y * 32;
    int layer = blockIdx.z;
    int tx = threadIdx.x & 31, ty = threadIdx.x >> 5;
    size_t rbase = ((size_t)layer * 4096 + oi0 + ty) * 64 + k0 + tx;
    tr[ty][tx] = wr[rbase];
    ti[ty][tx] = wi[rbase];
    __syncthreads();
    int k = k0 + ty;
    size_t wbase = ((size_t)(layer * 64 + k) * 2) * 4096 + oi0 + tx;
    g_wT[wbase]        = tr[tx][ty];
    g_wT[wbase + 4096] = ti[tx][ty];
}

// ---------------- lift (writes bf16 hi/lo) ----------------
__global__ __launch_bounds__(128) void lift_kernel(
    const float* __restrict__ u, const float* __restrict__ z,
    const float* __restrict__ w_lift, const float* __restrict__ b_lift,
    __nv_bfloat16* __restrict__ xh, __nv_bfloat16* __restrict__ xl)
{
    int b = blockIdx.y;
    int l = blockIdx.x * 128 + threadIdx.x;
    __shared__ float sw[64 * 16];
    __shared__ float sb[64];
    int t = threadIdx.x;
    for (int e = t; e < 1024; e += 128) sw[e] = w_lift[e];
    if (t < 64) sb[t] = b_lift[t];
    __syncthreads();
    float uv[16];
#pragma unroll
    for (int c = 0; c < 8; c++) uv[c] = u[((size_t)b * LDIM + l) * 8 + c];
#pragma unroll
    for (int c = 0; c < 8; c++) uv[8 + c] = z[b * 8 + c];
    for (int h = 0; h < 64; h++) {
        float acc = sb[h];
#pragma unroll
        for (int c = 0; c < 16; c++) acc += sw[h * 16 + c] * uv[c];
        size_t off = ((size_t)(b * 64 + h)) * LDIM + l;
        __nv_bfloat16 hi = __float2bfloat16(acc);
        xh[off] = hi;
        xl[off] = __float2bfloat16(acc - __bfloat162float(hi));
    }
}

// ---------------- forward DFT via mma.sync, 3-stage ring, XOR swizzle ----
#define DCHK 32
#define DTILE_B (128 * 64)              // 8192
#define DBUF_B (4 * DTILE_B)            // 32768
#define DSTAGES 3
#define DFT_SMEM (DSTAGES * DBUF_B)     // 98304
#define DNCHK (KPC / DCHK)              // 8

__device__ __forceinline__ void dft_stage(
    uint32_t sb, int buf, int lc, int bh0, int t,
    const __nv_bfloat16* xh, const __nv_bfloat16* xl)
{
#pragma unroll
    for (int i = 0; i < 8; i++) {
        const int tile = i >> 1;
        int q = t + 256 * (i & 1);
        int r = q >> 2, uu = q & 3;
        const __nv_bfloat16* src;
        if (tile == 0)      src = xh + ((size_t)(bh0 + r)) * LDIM;
        else if (tile == 1) src = xl + ((size_t)(bh0 + r)) * LDIM;
        else if (tile == 2) src = g_trigIh + (size_t)r * LDIM;
        else                src = g_trigIl + (size_t)r * LDIM;
        uint32_t dst = sb + buf * DBUF_B + tile * DTILE_B + r * 64
                       + ((uu ^ ((r >> 1) & 3)) << 4);
        CP_ASYNC16(dst, src + lc + uu * 8);
    }
    CP_COMMIT();
}

__global__ void __launch_bounds__(256, 2) dft_mma_kernel(
    const __nv_bfloat16* __restrict__ xh,
    const __nv_bfloat16* __restrict__ xl,
    float* __restrict__ cpart)
{
    extern __shared__ char smem[];
    uint32_t sb = smem_to_u32(smem);
    int t = threadIdx.x;
    int lane = t & 31, w = t >> 5;
    int wm = w & 3, wn = w >> 2;
    int bh0 = blockIdx.x * 128;
    int l0  = blockIdx.y * KPC;

    int lrow = lane & 15, lhi = lane >> 4;
    uint32_t arow[2], brow[4];
    uint32_t arsw[2], brsw[4];
#pragma unroll
    for (int mi = 0; mi < 2; mi++) {
        int row = 32 * wm + 16 * mi + lrow;
        arow[mi] = (uint32_t)(row * 64);
        arsw[mi] = (uint32_t)((row >> 1) & 3);
    }
#pragma unroll
    for (int ni = 0; ni < 4; ni++) {
        int row = 64 * wn + 16 * ni + lrow;
        brow[ni] = (uint32_t)(row * 64);
        brsw[ni] = (uint32_t)((row >> 1) & 3);
    }

    float d[2][8][4];
#pragma unroll
    for (int mi = 0; mi < 2; mi++)
#pragma unroll
        for (int ng = 0; ng < 8; ng++)
#pragma unroll
            for (int j = 0; j < 4; j++) d[mi][ng][j] = 0.f;

    dft_stage(sb, 0, l0, bh0, t, xh, xl);
    dft_stage(sb, 1, l0 + DCHK, bh0, t, xh, xl);

    for (int c = 0; c < DNCHK; c++) {
        if (c + 1 < DNCHK) CP_WAIT(1); else CP_WAIT(0);
        __syncthreads();
        if (c + 2 < DNCHK)
            dft_stage(sb, (c + 2) % DSTAGES, l0 + (c + 2) * DCHK, bh0, t, xh, xl);
        uint32_t base = sb + (c % DSTAGES) * DBUF_B;
#pragma unroll
        for (int s = 0; s < 2; s++) {
            uint32_t cl = (uint32_t)(s * 2) + (uint32_t)lhi;  // logical chunk
            uint32_t aH[2][4], aL[2][4], bHf[4][4], bLf[4][4];
#pragma unroll
            for (int mi = 0; mi < 2; mi++) {
                uint32_t aoff = arow[mi] + ((cl ^ arsw[mi]) << 4);
                LDMATRIX_X4(aH[mi][0], aH[mi][1], aH[mi][2], aH[mi][3],
                            base + 0 * DTILE_B + aoff);
                LDMATRIX_X4(aL[mi][0], aL[mi][1], aL[mi][2], aL[mi][3],
                            base + 1 * DTILE_B + aoff);
            }
#pragma unroll
            for (int ni = 0; ni < 4; ni++) {
                uint32_t boff = brow[ni] + ((cl ^ brsw[ni]) << 4);
                LDMATRIX_X4(bHf[ni][0], bHf[ni][1], bHf[ni][2], bHf[ni][3],
                            base + 2 * DTILE_B + boff);
                LDMATRIX_X4(bLf[ni][0], bLf[ni][1], bLf[ni][2], bLf[ni][3],
                            base + 3 * DTILE_B + boff);
            }
#pragma unroll
            for (int mi = 0; mi < 2; mi++)
#pragma unroll
                for (int ni = 0; ni < 4; ni++)
#pragma unroll
                    for (int sub = 0; sub < 2; sub++) {
                        int ng = ni * 2 + sub;
                        MMA_16816(d[mi][ng], aH[mi], bHf[ni][sub], bHf[ni][sub + 2]);
                        MMA_16816(d[mi][ng], aL[mi], bHf[ni][sub], bHf[ni][sub + 2]);
                        MMA_16816(d[mi][ng], aH[mi], bLf[ni][sub], bLf[ni][sub + 2]);
                    }
        }
    }

    float* cp = cpart + (size_t)blockIdx.y * BH * NK;
    int rbase = bh0 + 32 * wm + (lane >> 2);
    int cbase = 64 * wn + (lane & 3) * 2;
#pragma unroll
    for (int mi = 0; mi < 2; mi++) {
#pragma unroll
        for (int ng = 0; ng < 8; ng++) {
            int col = cbase + 8 * ng;
            int row = rbase + 16 * mi;
            *reinterpret_cast<float2*>(&cp[(size_t)row * NK + col]) =
                make_float2(d[mi][ng][0], d[mi][ng][1]);
            *reinterpret_cast<float2*>(&cp[(size_t)(row + 8) * NK + col]) =
                make_float2(d[mi][ng][2], d[mi][ng][3]);
        }
    }
}

// reduce split buffers -> xfT[kk][bh]
__global__ __launch_bounds__(256) void reduce_kernel(
    const float* __restrict__ cpart, float* __restrict__ xfT)
{
    int q = blockIdx.x * 256 + threadIdx.x;
    int idx = q * 4;
    int bh = idx >> 7, kk = idx & 127;
    float4 s = make_float4(0.f, 0.f, 0.f, 0.f);
#pragma unroll
    for (int p = 0; p < KSPLIT; p++) {
        float4 v = *reinterpret_cast<const float4*>(&cpart[(size_t)p * BH * NK + idx]);
        s.x += v.x; s.y += v.y; s.z += v.z; s.w += v.w;
    }
    xfT[(size_t)(kk + 0) * BH + bh] = s.x;
    xfT[(size_t)(kk + 1) * BH + bh] = s.y;
    xfT[(size_t)(kk + 2) * BH + bh] = s.z;
    xfT[(size_t)(kk + 3) * BH + bh] = s.w;
}

// ---------------- per-mode complex mix (also emits bf16 hi/lo) -----------
__global__ __launch_bounds__(512) void mix_kernel(
    const float* __restrict__ xfT, float* __restrict__ g,
    __nv_bfloat16* __restrict__ gh, __nv_bfloat16* __restrict__ gl, int layer)
{
    int k = blockIdx.x;
    __shared__ float swr[64][65];
    __shared__ float swi[64][65];
    __shared__ float sxr[64][32];
    __shared__ float sxi[64][32];
    int t = threadIdx.x;
    const float* wTr = g_wT + ((size_t)(layer * 64 + k) * 2) * 4096;
    for (int e = t; e < 4096; e += 512) {
        int o = e >> 6, i = e & 63;
        swr[o][i] = wTr[e];
        swi[o][i] = wTr[4096 + e];
    }
    for (int e = t; e < 2048; e += 512) {
        int b = e >> 6, i = e & 63;
        int bh = b * 64 + i;
        sxr[i][b] = xfT[(size_t)k * BH + bh];
        sxi[i][b] = xfT[(size_t)(64 + k) * BH + bh];
    }
    __syncthreads();
    int o = t >> 3;
    int b0 = (t & 7) * 4;
    float ar[4] = {0, 0, 0, 0}, ai[4] = {0, 0, 0, 0};
    for (int i = 0; i < 64; i++) {
        float wrv = swr[o][i], wiv = swi[o][i];
#pragma unroll
        for (int j = 0; j < 4; j++) {
            float xr = sxr[i][b0 + j], xi = sxi[i][b0 + j];
            ar[j] += xr * wrv - xi * wiv;
            ai[j] += xr * wiv + xi * wrv;
        }
    }
    float scl = (k == 0) ? (1.0f / LDIM) : (2.0f / LDIM);
#pragma unroll
    for (int j = 0; j < 4; j++) {
        int b = b0 + j;
        float vr = ar[j] * scl;
        float vi = (k == 0) ? 0.0f : ai[j] * scl;
        size_t offr = ((size_t)(b * 64 + o)) * NK + k;
        size_t offi = ((size_t)(b * 64 + o)) * NK + 64 + k;
        g[offr] = vr;
        g[offi] = vi;
        __nv_bfloat16 hr = __float2bfloat16(vr);
        __nv_bfloat16 hi2 = __float2bfloat16(vi);
        gh[offr] = hr;
        gl[offr] = __float2bfloat16(vr - __bfloat162float(hr));
        gh[offi] = hi2;
        gl[offi] = __float2bfloat16(vi - __bfloat162float(hi2));
    }
}

// ---------------- fused iDFT + skip + bias + gelu via mma.sync -----------
// grid (32 l-tiles of 128, 32 b). CTA 256 thr = 8 warps (4 m x 2 n).
// A tile staged via cp.async from pre-split gh/gl + wsh/wsl.
#define APITCH 200                          // bf16 per A row (400 B, 16-aligned)
#define A_TILE_B (64 * APITCH * 2)          // 25600
#define BPITCH 272                          // bytes per B row (128 bf16 + pad)
#define IBTILE_B (32 * BPITCH)              // 8704
#define IBUF_B (2 * IBTILE_B)               // 17408
#define ISTAGES 3
#define OFF_AH 0
#define OFF_AL (A_TILE_B)
#define OFF_B  (2 * A_TILE_B)
#define IDFT_SMEM (2 * A_TILE_B + ISTAGES * IBUF_B)   // 103424
#define INCHK 6

__device__ __forceinline__ void idft_stage(
    uint32_t sbu, int buf, int c, int b, int l0, int t,
    const __nv_bfloat16* xoldh, const __nv_bfloat16* xoldl)
{
#pragma unroll
    for (int i = 0; i < 4; i++) {
        const int tile = i >> 1;              // 0 = hi, 1 = lo
        int q = t + 256 * (i & 1);
        int r = q >> 4, uu = q & 15;
        const __nv_bfloat16* src;
        if (c < 4) src = (tile ? g_trigIl : g_trigIh) + (size_t)(c * 32 + r) * LDIM;
        else       src = (tile ? xoldl : xoldh)
                         + ((size_t)(b * 64 + (c - 4) * 32 + r)) * LDIM;
        uint32_t dst = sbu + OFF_B + buf * IBUF_B + tile * IBTILE_B
                       + r * BPITCH + uu * 16;
        CP_ASYNC16(dst, src + l0 + uu * 8);
    }
    CP_COMMIT();
}

__global__ void __launch_bounds__(256, 2) idft_mma_kernel(
    const __nv_bfloat16* __restrict__ gh, const __nv_bfloat16* __restrict__ gl,
    const __nv_bfloat16* __restrict__ xoldh, const __nv_bfloat16* __restrict__ xoldl,
    const float* __restrict__ b_skip,
    __nv_bfloat16* __restrict__ xnewh, __nv_bfloat16* __restrict__ xnewl, int layer)
{
    extern __shared__ char smem[];
    uint32_t sbu = smem_to_u32(smem);
    int t = threadIdx.x;
    int lane = t & 31, w = t >> 5;
    int wm = w & 3, wn = w >> 2;
    int b  = blockIdx.y;
    int l0 = blockIdx.x * 128;
    int lrow = lane & 15, lhi = lane >> 4;

    // stage A via cp.async: 64 rows x 24 chunks x {hi,lo} = 3072 chunks
#pragma unroll
    for (int i = 0; i < 12; i++) {
        int e = t + 256 * i;
        int hl = e >= 1536;
        int rem = hl ? (e - 1536) : e;
        int row = rem / 24;
        int ch = rem - row * 24;
        const __nv_bfloat16* src;
        if (ch < 16) src = (hl ? gl : gh) + ((size_t)(b * 64 + row)) * NK + ch * 8;
        else         src = (hl ? g_wsl : g_wsh)
                           + ((size_t)(layer * 64 + row)) * 64 + (ch - 16) * 8;
        uint32_t dst = sbu + (hl ? OFF_AL : OFF_AH) + row * (APITCH * 2) + ch * 16;
        CP_ASYNC16(dst, src);
    }
    // B chunk 0 joins the same commit group as A (committed inside idft_stage)
    idft_stage(sbu, 0, 0, b, l0, t, xoldh, xoldl);
    idft_stage(sbu, 1, 1, b, l0, t, xoldh, xoldl);

    float d[8][4];
    {
        float bs0 = b_skip[layer * 64 + wm * 16 + (lane >> 2)];
        float bs1 = b_skip[layer * 64 + wm * 16 + (lane >> 2) + 8];
#pragma unroll
        for (int ng = 0; ng < 8; ng++) {
            d[ng][0] = bs0; d[ng][1] = bs0;
            d[ng][2] = bs1; d[ng][3] = bs1;
        }
    }

    uint32_t aoff = (uint32_t)((wm * 16 + lrow) * (APITCH * 2) + lhi * 16);
    uint32_t boff[4];
#pragma unroll
    for (int ni = 0; ni < 4; ni++)
        boff[ni] = (uint32_t)(lrow * BPITCH + (wn * 64 + ni * 16) * 2 + lhi * 16);

    for (int c = 0; c < INCHK; c++) {
        if (c + 1 < INCHK) CP_WAIT(1); else CP_WAIT(0);
        __syncthreads();
        if (c + 2 < INCHK)
            idft_stage(sbu, (c + 2) % ISTAGES, c + 2, b, l0, t, xoldh, xoldl);
        uint32_t bbase = sbu + OFF_B + (c % ISTAGES) * IBUF_B;
#pragma unroll
        for (int s = 0; s < 2; s++) {
            uint32_t aH[4], aL[4], bHf[4][4], bLf[4][4];
            uint32_t ash = (uint32_t)((c * 2 + s) * 32);
            LDMATRIX_X4(aH[0], aH[1], aH[2], aH[3], sbu + OFF_AH + aoff + ash);
            LDMATRIX_X4(aL[0], aL[1], aL[2], aL[3], sbu + OFF_AL + aoff + ash);
            uint32_t bsh = (uint32_t)(s * 16 * BPITCH);
#pragma unroll
            for (int ni = 0; ni < 4; ni++) {
                LDMATRIX_X4_T(bHf[ni][0], bHf[ni][1], bHf[ni][2], bHf[ni][3],
                              bbase + 0 * IBTILE_B + bsh + boff[ni]);
                LDMATRIX_X4_T(bLf[ni][0], bLf[ni][1], bLf[ni][2], bLf[ni][3],
                              bbase + 1 * IBTILE_B + bsh + boff[ni]);
            }
#pragma unroll
            for (int ni = 0; ni < 4; ni++)
#pragma unroll
                for (int sub = 0; sub < 2; sub++) {
                    int ng = ni * 2 + sub;
                    MMA_16816(d[ng], aH, bHf[ni][2 * sub], bHf[ni][2 * sub + 1]);
                    MMA_16816(d[ng], aL, bHf[ni][2 * sub], bHf[ni][2 * sub + 1]);
                    MMA_16816(d[ng], aH, bLf[ni][2 * sub], bLf[ni][2 * sub + 1]);
                }
        }
    }

    int o0 = wm * 16 + (lane >> 2);
    int lc = l0 + wn * 64 + (lane & 3) * 2;
#pragma unroll
    for (int ng = 0; ng < 8; ng++) {
        int l = lc + ng * 8;
#pragma unroll
        for (int half = 0; half < 2; half++) {
            int o = o0 + 8 * half;
            float vx = gelu_fast(d[ng][2 * half]);
            float vy = gelu_fast(d[ng][2 * half + 1]);
            __nv_bfloat162 h2 = __floats2bfloat162_rn(vx, vy);
            float2 hv = __bfloat1622float2(h2);
            __nv_bfloat162 l2 = __floats2bfloat162_rn(vx - hv.x, vy - hv.y);
            size_t off = ((size_t)(b * 64 + o)) * LDIM + l;
            *reinterpret_cast<__nv_bfloat162*>(&xnewh[off]) = h2;
            *reinterpret_cast<__nv_bfloat162*>(&xnewl[off]) = l2;
        }
    }
}

// ---------------- layer-3 point eval + projection ----------------
__global__ __launch_bounds__(128) void final_kernel(
    const float* __restrict__ g,
    const __nv_bfloat16* __restrict__ x3h, const __nv_bfloat16* __restrict__ x3l,
    const float* __restrict__ w_skip, const float* __restrict__ b_skip,
    const float* __restrict__ w_p1, const float* __restrict__ b_p1,
    const float* __restrict__ w_p2, const float* __restrict__ b_p2,
    float* __restrict__ out)
{
    int b = blockIdx.x;
    int t = threadIdx.x;
    __shared__ float sv[64];
    __shared__ float sh[128];
    __shared__ float sxl[64];
    __shared__ float sc[64], ss[64];
    if (t < 64) {
        size_t off = ((size_t)(b * 64 + t)) * LDIM + (LDIM - 1);
        sxl[t] = __bfloat162float(x3h[off]) + __bfloat162float(x3l[off]);
        float sn, cn;
        sincospif((float)t / 2048.0f, &sn, &cn);
        sc[t] = cn; ss[t] = sn;
    }
    __syncthreads();
    if (t < 64) {
        int o = t;
        float acc = b_skip[3 * 64 + o];
        const float* go = g + ((size_t)(b * 64 + o)) * NK;
        for (int k = 0; k < 64; k++)
            acc += go[k] * sc[k] + go[64 + k] * ss[k];
        for (int i = 0; i < 64; i++)
            acc += w_skip[(3 * 64 + o) * 64 + i] * sxl[i];
        sv[o] = acc;
    }
    __syncthreads();
    {
        int p = t;
        float acc = b_p1[p];
        for (int o = 0; o < 64; o++) acc += w_p1[p * 64 + o] * sv[o];
        sh[p] = gelu_tanh(acc);
    }
    __syncthreads();
    if (t < 8) {
        float acc = b_p2[t];
        for (int p = 0; p < 128; p++) acc += w_p2[t * 128 + p] * sh[p];
        out[b * 8 + t] = acc;
    }
}

// ---------------- host launcher ------------------------------------------
extern "C" void kernel_launch(void* const* d_in, const int* in_sizes, int n_in,
                              void* d_out, int out_size)
{
    const float* u       = (const float*)d_in[0];
    const float* z       = (const float*)d_in[1];
    const float* w_lift  = (const float*)d_in[3];
    const float* b_lift  = (const float*)d_in[4];
    const float* spec_wr = (const float*)d_in[5];
    const float* spec_wi = (const float*)d_in[6];
    const float* w_skip  = (const float*)d_in[7];
    const float* b_skip  = (const float*)d_in[8];
    const float* w_p1    = (const float*)d_in[9];
    const float* b_p1    = (const float*)d_in[10];
    const float* w_p2    = (const float*)d_in[11];
    const float* b_p2    = (const float*)d_in[12];
    float* out = (float*)d_out;

    void *px0h, *px0l, *px1h, *px1l, *pcp, *pxf, *pgg, *pgh, *pgl;
    cudaGetSymbolAddress(&px0h, g_x0h);
    cudaGetSymbolAddress(&px0l, g_x0l);
    cudaGetSymbolAddress(&px1h, g_x1h);
    cudaGetSymbolAddress(&px1l, g_x1l);
    cudaGetSymbolAddress(&pcp, g_cpart);
    cudaGetSymbolAddress(&pxf, g_xfT);
    cudaGetSymbolAddress(&pgg, g_g);
    cudaGetSymbolAddress(&pgh, g_gh);
    cudaGetSymbolAddress(&pgl, g_gl);

    cudaFuncSetAttribute(dft_mma_kernel,
                         cudaFuncAttributeMaxDynamicSharedMemorySize, DFT_SMEM);
    cudaFuncSetAttribute(idft_mma_kernel,
                         cudaFuncAttributeMaxDynamicSharedMemorySize, IDFT_SMEM);

    trig_kernel<<<(NK * LDIM) / 256, 256>>>();
    wskip_kernel<<<(4 * 64 * 64) / 256, 256>>>(w_skip);
    wtrans_kernel<<<dim3(128, 2, 4), 1024>>>(spec_wr, spec_wi);
    lift_kernel<<<dim3(32, 32), 128>>>(u, z, w_lift, b_lift,
                                       (__nv_bfloat16*)px0h, (__nv_bfloat16*)px0l);

    __nv_bfloat16* xch = (__nv_bfloat16*)px0h;
    __nv_bfloat16* xcl = (__nv_bfloat16*)px0l;
    __nv_bfloat16* xnh = (__nv_bfloat16*)px1h;
    __nv_bfloat16* xnl = (__nv_bfloat16*)px1l;
    for (int layer = 0; layer < 4; layer++) {
        dft_mma_kernel<<<dim3(16, KSPLIT), 256, DFT_SMEM>>>(xch, xcl, (float*)pcp);
        reduce_kernel<<<(BH * NK / 4) / 256, 256>>>((float*)pcp, (float*)pxf);
        mix_kernel<<<64, 512>>>((float*)pxf, (float*)pgg,
                                (__nv_bfloat16*)pgh, (__nv_bfloat16*)pgl, layer);
        if (layer < 3) {
            idft_mma_kernel<<<dim3(32, 32), 256, IDFT_SMEM>>>(
                (__nv_bfloat16*)pgh, (__nv_bfloat16*)pgl, xch, xcl,
                b_skip, xnh, xnl, layer);
            __nv_bfloat16* th = xch; xch = xnh; xnh = th;
            __nv_bfloat16* tl = xcl; xcl = xnl; xnl = tl;
        }
    }
    final_kernel<<<32, 128>>>((float*)pgg, xch, xcl, w_skip, b_skip,
                              w_p1, b_p1, w_p2, b_p2, out);
}